// round 2
// baseline (speedup 1.0000x reference)
#include <cuda_runtime.h>
#include <cuda_bf16.h>

// Problem constants
#define BDIM 64
#define SLEN 2048
#define EH 512
#define AH 512
#define NCHUNK 16          // S chunks per batch row
#define BS 128             // S rows per CTA
#define KT 32              // K tile
#define NT 128             // N tile
#define KPAD 36            // KT + 4 pad: conflict-free for frag reads & STS.128
#define THREADS 256

// Scratch (device globals; no dynamic allocation allowed)
__device__ float g_dec_proj[BDIM * AH];
__device__ float g_expscore[BDIM * SLEN];
__device__ float g_cp[BDIM * NCHUNK * EH];   // context partials
__device__ float g_den[BDIM * NCHUNK];       // softmax denominator partials

__device__ __forceinline__ float tanh_fast(float x) {
    float y;
    asm("tanh.approx.f32 %0, %1;" : "=f"(y) : "f"(x));
    return y;
}

__device__ __forceinline__ unsigned f2tf(float x) {
    unsigned u;
    asm("cvt.rna.tf32.f32 %0, %1;" : "=r"(u) : "f"(x));
    return u;
}

__device__ __forceinline__ void mma_tf32(float c[4], const unsigned a[4],
                                         unsigned b0, unsigned b1) {
    asm volatile(
        "mma.sync.aligned.m16n8k8.row.col.f32.tf32.tf32.f32 "
        "{%0,%1,%2,%3},{%4,%5,%6,%7},{%8,%9},{%0,%1,%2,%3};\n"
        : "+f"(c[0]), "+f"(c[1]), "+f"(c[2]), "+f"(c[3])
        : "r"(a[0]), "r"(a[1]), "r"(a[2]), "r"(a[3]), "r"(b0), "r"(b1));
}

__device__ __forceinline__ uint4 cvt4(float4 v) {
    uint4 u;
    u.x = f2tf(v.x); u.y = f2tf(v.y); u.z = f2tf(v.z); u.w = f2tf(v.w);
    return u;
}

// ---------------------------------------------------------------------------
// Kernel 1: dec_proj[b][a] = dec_hidden[b] . W_dec[a]   (fp32, exact)
// ---------------------------------------------------------------------------
__global__ void dec_proj_kernel(const float* __restrict__ dec_hidden,
                                const float* __restrict__ W_dec) {
    __shared__ float sH[EH];
    const int b = blockIdx.x;
    const int t = threadIdx.x;
    for (int i = t; i < EH; i += blockDim.x) sH[i] = dec_hidden[b * EH + i];
    __syncthreads();
    for (int a = t; a < AH; a += blockDim.x) {
        const float* wr = W_dec + (size_t)a * EH;
        float s = 0.f;
#pragma unroll 8
        for (int d = 0; d < EH; d++) s += wr[d] * sH[d];
        g_dec_proj[b * AH + a] = s;
    }
}

// ---------------------------------------------------------------------------
// Kernel 2 (main, fused): for each (b, s-chunk of 128):
//   score[s]   = sum_a tanh(enc[s].W_enc[a] + dec_proj[b][a]) * v[a]
//   exp(score) -> g_expscore, partial denominator -> g_den
//   partial context cp[e] = sum_s exp(score_s) * enc[s][e] -> g_cp
// GEMM via mma.sync m16n8k8 tf32, fp32 accumulate. Operands are converted to
// tf32 ONCE at STS time (smem holds tf32 bit patterns), and the next K-slab
// is prefetched into registers while the current slab's MMAs run.
// ---------------------------------------------------------------------------
__global__ __launch_bounds__(THREADS, 2) void score_ctx_kernel(
    const float* __restrict__ enc, const float* __restrict__ W,
    const float* __restrict__ v) {
    __shared__ unsigned sEnc[BS][KPAD];   // tf32 bits
    __shared__ unsigned sW[NT][KPAD];     // tf32 bits
    __shared__ float sDec[AH];
    __shared__ float sV[AH];
    __shared__ float sPart[2][BS];
    __shared__ float sRed[BS];

    const int chunk = blockIdx.x, b = blockIdx.y;
    const int s0 = chunk * BS;
    const int t = threadIdx.x;
    const int lane = t & 31, wid = t >> 5;
    const int wm = wid >> 1;   // 0..3 : 32-row slab
    const int wn = wid & 1;    // 0..1 : 64-col slab
    const int q = lane >> 2;   // group id (0..7)
    const int tg = lane & 3;   // thread-in-group (0..3)

    for (int i = t; i < AH; i += THREADS) {
        sDec[i] = g_dec_proj[b * AH + i];
        sV[i] = v[i];
    }

    const float* encB = enc + ((size_t)b * SLEN + s0) * EH;

    // per-thread tile coordinates for the cooperative loads
    const int ldr[4] = { (t + 0 * THREADS) >> 3, (t + 1 * THREADS) >> 3,
                         (t + 2 * THREADS) >> 3, (t + 3 * THREADS) >> 3 };
    const int ldc = (t & 7) * 4;

    float rowsum[4] = {0.f, 0.f, 0.f, 0.f};

    for (int nt = 0; nt < AH / NT; nt++) {
        float acc[2][8][4];
#pragma unroll
        for (int mi = 0; mi < 2; mi++)
#pragma unroll
            for (int ni = 0; ni < 8; ni++)
#pragma unroll
                for (int j = 0; j < 4; j++) acc[mi][ni][j] = 0.f;

        const float* Wn = W + (size_t)(nt * NT) * EH;

        // prefetch kt=0 into registers
        float4 pe[4], pw[4];
#pragma unroll
        for (int rep = 0; rep < 4; rep++) {
            pe[rep] = *reinterpret_cast<const float4*>(
                encB + (size_t)ldr[rep] * EH + ldc);
            pw[rep] = *reinterpret_cast<const float4*>(
                Wn + (size_t)ldr[rep] * EH + ldc);
        }

        for (int kt = 0; kt < EH / KT; kt++) {
            __syncthreads();   // previous compute done before overwrite
#pragma unroll
            for (int rep = 0; rep < 4; rep++) {
                *reinterpret_cast<uint4*>(&sEnc[ldr[rep]][ldc]) = cvt4(pe[rep]);
                *reinterpret_cast<uint4*>(&sW[ldr[rep]][ldc]) = cvt4(pw[rep]);
            }
            __syncthreads();

            if (kt < EH / KT - 1) {
                const int koff = (kt + 1) * KT + ldc;
#pragma unroll
                for (int rep = 0; rep < 4; rep++) {
                    pe[rep] = *reinterpret_cast<const float4*>(
                        encB + (size_t)ldr[rep] * EH + koff);
                    pw[rep] = *reinterpret_cast<const float4*>(
                        Wn + (size_t)ldr[rep] * EH + koff);
                }
            }

#pragma unroll
            for (int kk = 0; kk < KT / 8; kk++) {
                const int k0 = kk * 8;
                unsigned afr[2][4];
#pragma unroll
                for (int mi = 0; mi < 2; mi++) {
                    int r0 = wm * 32 + mi * 16 + q;
                    afr[mi][0] = sEnc[r0][k0 + tg];
                    afr[mi][1] = sEnc[r0 + 8][k0 + tg];
                    afr[mi][2] = sEnc[r0][k0 + tg + 4];
                    afr[mi][3] = sEnc[r0 + 8][k0 + tg + 4];
                }
#pragma unroll
                for (int ni = 0; ni < 8; ni++) {
                    int n = wn * 64 + ni * 8 + q;
                    unsigned b0 = sW[n][k0 + tg];
                    unsigned b1 = sW[n][k0 + tg + 4];
                    mma_tf32(acc[0][ni], afr[0], b0, b1);
                    mma_tf32(acc[1][ni], afr[1], b0, b1);
                }
            }
        }

        // Epilogue for this n-tile: tanh(proj + dec) * v, reduce over cols.
        // C frag: c0=(row, 2tg), c1=(row, 2tg+1), c2=(row+8, 2tg), c3=(row+8, 2tg+1)
#pragma unroll
        for (int mi = 0; mi < 2; mi++) {
#pragma unroll
            for (int ni = 0; ni < 8; ni++) {
                int col = nt * NT + wn * 64 + ni * 8 + tg * 2;
                float t0 = tanh_fast(acc[mi][ni][0] + sDec[col]) * sV[col];
                float t1 = tanh_fast(acc[mi][ni][1] + sDec[col + 1]) * sV[col + 1];
                float t2 = tanh_fast(acc[mi][ni][2] + sDec[col]) * sV[col];
                float t3 = tanh_fast(acc[mi][ni][3] + sDec[col + 1]) * sV[col + 1];
                rowsum[mi * 2] += t0 + t1;       // row = wm*32 + mi*16 + q
                rowsum[mi * 2 + 1] += t2 + t3;   // row + 8
            }
        }
    }

    // Reduce across the 4 quad lanes (they own the same rows, different cols)
#pragma unroll
    for (int j = 0; j < 4; j++) {
        rowsum[j] += __shfl_xor_sync(0xffffffffu, rowsum[j], 1);
        rowsum[j] += __shfl_xor_sync(0xffffffffu, rowsum[j], 2);
    }
    if (tg == 0) {
        sPart[wn][wm * 32 + q] = rowsum[0];
        sPart[wn][wm * 32 + q + 8] = rowsum[1];
        sPart[wn][wm * 32 + q + 16] = rowsum[2];
        sPart[wn][wm * 32 + q + 24] = rowsum[3];
    }
    __syncthreads();

    // score -> exp (scores bounded ~±2; unnormalized softmax is exact math)
    if (t < BS) {
        float sc = sPart[0][t] + sPart[1][t];
        float ex = __expf(sc);
        g_expscore[b * SLEN + s0 + t] = ex;
        sRed[t] = ex;
    }
    __syncthreads();

    // deterministic denominator partial
    if (t < 32) {
        float d = sRed[t] + sRed[t + 32] + sRed[t + 64] + sRed[t + 96];
#pragma unroll
        for (int off = 16; off; off >>= 1)
            d += __shfl_xor_sync(0xffffffffu, d, off);
        if (t == 0) g_den[b * NCHUNK + chunk] = d;
    }
    __syncthreads();

    // Partial weighted context: each thread owns 2 of 512 e-columns (coalesced;
    // encB tile was just read, so this hits L2)
    float cp0 = 0.f, cp1 = 0.f;
    const int e0 = t, e1 = t + THREADS;
#pragma unroll 4
    for (int r = 0; r < BS; r++) {
        float w = sRed[r];
        cp0 += w * encB[(size_t)r * EH + e0];
        cp1 += w * encB[(size_t)r * EH + e1];
    }
    g_cp[((size_t)(b * NCHUNK + chunk)) * EH + e0] = cp0;
    g_cp[((size_t)(b * NCHUNK + chunk)) * EH + e1] = cp1;
}

// ---------------------------------------------------------------------------
// Kernel 3: finalize. context = sum(cp)/den ; attn_weights = expscore/den
// Output layout: [context (64*512)] then [attn_weights (64*2048)]
// ---------------------------------------------------------------------------
__global__ void finalize_kernel(float* __restrict__ out) {
    __shared__ float sInv;
    const int b = blockIdx.x;
    const int t = threadIdx.x;
    if (t == 0) {
        float d = 0.f;
#pragma unroll
        for (int c = 0; c < NCHUNK; c++) d += g_den[b * NCHUNK + c];
        sInv = 1.0f / d;
    }
    __syncthreads();
    const float inv = sInv;
    for (int e = t; e < EH; e += blockDim.x) {
        float s = 0.f;
#pragma unroll
        for (int c = 0; c < NCHUNK; c++) s += g_cp[(b * NCHUNK + c) * EH + e];
        out[b * EH + e] = s * inv;
    }
    float* wout = out + BDIM * EH;
    for (int s_ = t; s_ < SLEN; s_ += blockDim.x)
        wout[b * SLEN + s_] = g_expscore[b * SLEN + s_] * inv;
}

// ---------------------------------------------------------------------------
extern "C" void kernel_launch(void* const* d_in, const int* in_sizes, int n_in,
                              void* d_out, int out_size) {
    const float* enc = (const float*)d_in[0];      // [64, 2048, 512]
    const float* dec = (const float*)d_in[1];      // [64, 512]
    const float* W_enc = (const float*)d_in[2];    // [512, 512]
    const float* W_dec = (const float*)d_in[3];    // [512, 512]
    const float* v = (const float*)d_in[4];        // [1, 512]

    dec_proj_kernel<<<BDIM, 256>>>(dec, W_dec);
    score_ctx_kernel<<<dim3(NCHUNK, BDIM), THREADS>>>(enc, W_enc, v);
    finalize_kernel<<<BDIM, 256>>>((float*)d_out);
}

// round 4
// speedup vs baseline: 1.6496x; 1.6496x over previous
#include <cuda_runtime.h>
#include <cuda_bf16.h>

// Problem constants
#define BDIM 64
#define SLEN 2048
#define EH 512
#define AH 512
#define NCHUNK 16          // S chunks per batch row
#define BS 128             // S rows per CTA
#define KT 32              // K elems per stage
#define KW 16              // uint32 (bf16x2) words per row
#define KPADW 18           // padded words (conflict-free frag reads)
#define NT 128             // N tile
#define THREADS 256

// Scratch (device globals; no dynamic allocation allowed)
__device__ float g_dec_proj[BDIM * AH];
__device__ float g_expscore[BDIM * SLEN];
__device__ float g_cp[BDIM * NCHUNK * EH];   // context partials
__device__ float g_den[BDIM * NCHUNK];       // softmax denominator partials

__device__ __forceinline__ float tanh_fast(float x) {
    float y;
    asm("tanh.approx.f32 %0, %1;" : "=f"(y) : "f"(x));
    return y;
}

__device__ __forceinline__ void mma_bf16(float c[4], const unsigned a[4],
                                         unsigned b0, unsigned b1) {
    asm volatile(
        "mma.sync.aligned.m16n8k16.row.col.f32.bf16.bf16.f32 "
        "{%0,%1,%2,%3},{%4,%5,%6,%7},{%8,%9},{%0,%1,%2,%3};\n"
        : "+f"(c[0]), "+f"(c[1]), "+f"(c[2]), "+f"(c[3])
        : "r"(a[0]), "r"(a[1]), "r"(a[2]), "r"(a[3]), "r"(b0), "r"(b1));
}

// float4 -> 2 packed bf16x2 words (round-to-nearest)
__device__ __forceinline__ uint2 cvt4bf(float4 v) {
    __nv_bfloat162 lo = __float22bfloat162_rn(make_float2(v.x, v.y));
    __nv_bfloat162 hi = __float22bfloat162_rn(make_float2(v.z, v.w));
    uint2 u;
    u.x = *reinterpret_cast<unsigned*>(&lo);
    u.y = *reinterpret_cast<unsigned*>(&hi);
    return u;
}

// ---------------------------------------------------------------------------
// Kernel 1: dec_proj[b][a] = dec_hidden[b] . W_dec[a]   (fp32, exact)
// grid (8, 64): block y=b, x=slab of 64 outputs. One warp -> 8 outputs.
// ---------------------------------------------------------------------------
__global__ void dec_proj_kernel(const float* __restrict__ dec_hidden,
                                const float* __restrict__ W_dec) {
    __shared__ float sH[EH];
    const int b = blockIdx.y;
    const int t = threadIdx.x;
    const int lane = t & 31, wid = t >> 5;
    for (int i = t; i < EH; i += blockDim.x) sH[i] = dec_hidden[b * EH + i];
    __syncthreads();
#pragma unroll
    for (int i = 0; i < 8; i++) {
        const int a = blockIdx.x * 64 + wid * 8 + i;
        const float* wr = W_dec + (size_t)a * EH;
        float s = 0.f;
#pragma unroll
        for (int p = 0; p < 4; p++) {
            float4 w4 = *reinterpret_cast<const float4*>(wr + p * 128 + lane * 4);
            const float* h = sH + p * 128 + lane * 4;
            s += w4.x * h[0] + w4.y * h[1] + w4.z * h[2] + w4.w * h[3];
        }
#pragma unroll
        for (int off = 16; off; off >>= 1)
            s += __shfl_xor_sync(0xffffffffu, s, off);
        if (lane == 0) g_dec_proj[b * AH + a] = s;
    }
}

// ---------------------------------------------------------------------------
// Kernel 2 (main, fused): per (b, s-chunk of 128):
//   score[s] = sum_a tanh(enc[s].W_enc[a] + dec_proj[b][a]) * v[a]
//   exp(score) -> g_expscore, denominator partial -> g_den
//   partial context cp[e] = sum_s exp(score_s)*enc[s][e] -> g_cp
// GEMM via mma.sync m16n8k16 bf16 (2x legacy tf32 rate), fp32 accumulate.
// Operands converted to bf16 once at STS; next K-slab prefetched in regs.
// ---------------------------------------------------------------------------
__global__ __launch_bounds__(THREADS, 2) void score_ctx_kernel(
    const float* __restrict__ enc, const float* __restrict__ W,
    const float* __restrict__ v) {
    __shared__ unsigned sEnc[BS][KPADW];   // bf16x2 words
    __shared__ unsigned sW[NT][KPADW];
    __shared__ float sDec[AH];
    __shared__ float sV[AH];
    __shared__ float sPart[2][BS];
    __shared__ float sRed[BS];

    const int chunk = blockIdx.x, b = blockIdx.y;
    const int s0 = chunk * BS;
    const int t = threadIdx.x;
    const int lane = t & 31, wid = t >> 5;
    const int wm = wid >> 1;   // 0..3 : 32-row slab
    const int wn = wid & 1;    // 0..1 : 64-col slab
    const int q = lane >> 2;   // group id (0..7)
    const int tg = lane & 3;   // thread-in-group (0..3)

    for (int i = t; i < AH; i += THREADS) {
        sDec[i] = g_dec_proj[b * AH + i];
        sV[i] = v[i];
    }

    const float* encB = enc + ((size_t)b * SLEN + s0) * EH;

    // cooperative-load coordinates: 4 reps cover 128 rows x 32 floats per tile
    const int ldr[4] = { (t + 0 * THREADS) >> 3, (t + 1 * THREADS) >> 3,
                         (t + 2 * THREADS) >> 3, (t + 3 * THREADS) >> 3 };
    const int ldc = (t & 7) * 4;        // float element col
    const int ldw = (t & 7) * 2;        // word col in smem

    float rowsum[4] = {0.f, 0.f, 0.f, 0.f};

#pragma unroll
    for (int nt = 0; nt < AH / NT; nt++) {
        float acc[2][8][4];
#pragma unroll
        for (int mi = 0; mi < 2; mi++)
#pragma unroll
            for (int ni = 0; ni < 8; ni++)
#pragma unroll
                for (int j = 0; j < 4; j++) acc[mi][ni][j] = 0.f;

        const float* Wn = W + (size_t)(nt * NT) * EH;

        // prefetch kt=0
        float4 pe[4], pw[4];
#pragma unroll
        for (int rep = 0; rep < 4; rep++) {
            pe[rep] = *reinterpret_cast<const float4*>(
                encB + (size_t)ldr[rep] * EH + ldc);
            pw[rep] = *reinterpret_cast<const float4*>(
                Wn + (size_t)ldr[rep] * EH + ldc);
        }

        for (int kt = 0; kt < EH / KT; kt++) {
            __syncthreads();   // previous compute done before overwrite
#pragma unroll
            for (int rep = 0; rep < 4; rep++) {
                *reinterpret_cast<uint2*>(&sEnc[ldr[rep]][ldw]) = cvt4bf(pe[rep]);
                *reinterpret_cast<uint2*>(&sW[ldr[rep]][ldw]) = cvt4bf(pw[rep]);
            }
            __syncthreads();

            if (kt < EH / KT - 1) {
                const int koff = (kt + 1) * KT + ldc;
#pragma unroll
                for (int rep = 0; rep < 4; rep++) {
                    pe[rep] = *reinterpret_cast<const float4*>(
                        encB + (size_t)ldr[rep] * EH + koff);
                    pw[rep] = *reinterpret_cast<const float4*>(
                        Wn + (size_t)ldr[rep] * EH + koff);
                }
            }

            // 2 k-steps of 16: m16n8k16 bf16 MMAs
#pragma unroll
            for (int kk = 0; kk < 2; kk++) {
                const int k0 = kk * 8;   // word offset
                unsigned afr[2][4];
#pragma unroll
                for (int mi = 0; mi < 2; mi++) {
                    int r0 = wm * 32 + mi * 16 + q;
                    afr[mi][0] = sEnc[r0][k0 + tg];
                    afr[mi][1] = sEnc[r0 + 8][k0 + tg];
                    afr[mi][2] = sEnc[r0][k0 + tg + 4];
                    afr[mi][3] = sEnc[r0 + 8][k0 + tg + 4];
                }
#pragma unroll
                for (int ni = 0; ni < 8; ni++) {
                    int n = wn * 64 + ni * 8 + q;
                    unsigned b0 = sW[n][k0 + tg];
                    unsigned b1 = sW[n][k0 + tg + 4];
                    mma_bf16(acc[0][ni], afr[0], b0, b1);
                    mma_bf16(acc[1][ni], afr[1], b0, b1);
                }
            }
        }

        // Epilogue: tanh(proj + dec) * v, reduce over cols.
        // C frag: c0=(row,2tg) c1=(row,2tg+1) c2=(row+8,2tg) c3=(row+8,2tg+1)
#pragma unroll
        for (int mi = 0; mi < 2; mi++) {
#pragma unroll
            for (int ni = 0; ni < 8; ni++) {
                int col = nt * NT + wn * 64 + ni * 8 + tg * 2;
                float t0 = tanh_fast(acc[mi][ni][0] + sDec[col]) * sV[col];
                float t1 = tanh_fast(acc[mi][ni][1] + sDec[col + 1]) * sV[col + 1];
                float t2 = tanh_fast(acc[mi][ni][2] + sDec[col]) * sV[col];
                float t3 = tanh_fast(acc[mi][ni][3] + sDec[col + 1]) * sV[col + 1];
                rowsum[mi * 2] += t0 + t1;       // row
                rowsum[mi * 2 + 1] += t2 + t3;   // row + 8
            }
        }
    }

    // Reduce across the 4 quad lanes (same rows, different cols)
#pragma unroll
    for (int j = 0; j < 4; j++) {
        rowsum[j] += __shfl_xor_sync(0xffffffffu, rowsum[j], 1);
        rowsum[j] += __shfl_xor_sync(0xffffffffu, rowsum[j], 2);
    }
    if (tg == 0) {
        sPart[wn][wm * 32 + q] = rowsum[0];
        sPart[wn][wm * 32 + q + 8] = rowsum[1];
        sPart[wn][wm * 32 + q + 16] = rowsum[2];
        sPart[wn][wm * 32 + q + 24] = rowsum[3];
    }
    __syncthreads();

    // score -> exp (scores bounded ~±2; unnormalized softmax is exact math)
    if (t < BS) {
        float sc = sPart[0][t] + sPart[1][t];
        float ex = __expf(sc);
        g_expscore[b * SLEN + s0 + t] = ex;
        sRed[t] = ex;
    }
    __syncthreads();

    // deterministic denominator partial
    if (t < 32) {
        float d = sRed[t] + sRed[t + 32] + sRed[t + 64] + sRed[t + 96];
#pragma unroll
        for (int off = 16; off; off >>= 1)
            d += __shfl_xor_sync(0xffffffffu, d, off);
        if (t == 0) g_den[b * NCHUNK + chunk] = d;
    }
    __syncthreads();

    // Partial weighted context (fp32 enc, exact weights path): 2 cols/thread
    float cp0 = 0.f, cp1 = 0.f;
    const int e0 = t, e1 = t + THREADS;
#pragma unroll 4
    for (int r = 0; r < BS; r++) {
        float w = sRed[r];
        cp0 += w * encB[(size_t)r * EH + e0];
        cp1 += w * encB[(size_t)r * EH + e1];
    }
    g_cp[((size_t)(b * NCHUNK + chunk)) * EH + e0] = cp0;
    g_cp[((size_t)(b * NCHUNK + chunk)) * EH + e1] = cp1;
}

// ---------------------------------------------------------------------------
// Kernel 3: finalize. grid (64, 5): y==0 -> context, y=1..4 -> weight slabs.
// Output layout: [context (64*512)] then [attn_weights (64*2048)]
// ---------------------------------------------------------------------------
__global__ void finalize_kernel(float* __restrict__ out) {
    __shared__ float sInv;
    const int b = blockIdx.x;
    const int part = blockIdx.y;
    const int t = threadIdx.x;
    if (t == 0) {
        float d = 0.f;
#pragma unroll
        for (int c = 0; c < NCHUNK; c++) d += g_den[b * NCHUNK + c];
        sInv = 1.0f / d;
    }
    __syncthreads();
    const float inv = sInv;
    if (part == 0) {
        for (int e = t; e < EH; e += blockDim.x) {
            float s = 0.f;
#pragma unroll
            for (int c = 0; c < NCHUNK; c++) s += g_cp[(b * NCHUNK + c) * EH + e];
            out[b * EH + e] = s * inv;
        }
    } else {
        float* wout = out + BDIM * EH;
        const int s0 = (part - 1) * 512;
        for (int s_ = t; s_ < 512; s_ += blockDim.x)
            wout[b * SLEN + s0 + s_] = g_expscore[b * SLEN + s0 + s_] * inv;
    }
}

// ---------------------------------------------------------------------------
extern "C" void kernel_launch(void* const* d_in, const int* in_sizes, int n_in,
                              void* d_out, int out_size) {
    const float* enc = (const float*)d_in[0];      // [64, 2048, 512]
    const float* dec = (const float*)d_in[1];      // [64, 512]
    const float* W_enc = (const float*)d_in[2];    // [512, 512]
    const float* W_dec = (const float*)d_in[3];    // [512, 512]
    const float* v = (const float*)d_in[4];        // [1, 512]

    dec_proj_kernel<<<dim3(8, BDIM), 256>>>(dec, W_dec);
    score_ctx_kernel<<<dim3(NCHUNK, BDIM), THREADS>>>(enc, W_enc, v);
    finalize_kernel<<<dim3(BDIM, 5), 256>>>((float*)d_out);
}